// round 1
// baseline (speedup 1.0000x reference)
#include <cuda_runtime.h>
#include <math.h>

#define HW 16384
#define NB 8
#define MROWS (NB*HW)      // 131072
#define HID 512
#define FD 128
#define NTOK 256
#define PI_D 3.14159265358979323846

// ---------------- scratch (device globals; no allocation) ----------------
__device__ float g_gammaQ[HW*FD];
__device__ float g_gammaL[3ull*HW*FD];
__device__ float g_tvals[HW];
__device__ float g_xq[HW*HID];
__device__ float g_qbuf[HW*FD];
__device__ float g_kv[2048*256];
__device__ float g_attn[(unsigned long long)MROWS*FD];
__device__ float g_hl[3ull*HW*HID];
__device__ float g_wf[3*FD*HID];
__device__ float g_bf[3*HID];
__device__ float g_m0[(unsigned long long)MROWS*HID];
__device__ float g_s[(unsigned long long)MROWS*HID];
__device__ float g_hv1[(unsigned long long)MROWS*HID];
__device__ float g_hv2[(unsigned long long)MROWS*HID];

// ---------------- Fourier feature + t-value kernel ----------------
__global__ void gamma_k(const float* __restrict__ x, float* __restrict__ gq,
                        float* __restrict__ gl, float* __restrict__ tv)
{
    int q = blockIdx.x;
    int f = threadIdx.x;     // 0..127
    float c0 = x[2*q], c1 = x[2*q+1];
    if (f == 0) {
        int r  = (int)(c0 * 16.0f);
        int cc = (int)(c1 * 16.0f);
        tv[q] = (float)(r*16 + cc) * (1.0f/256.0f);
    }
    int d = f >> 6;          // input dim 0/1
    int rr = f & 63;
    int part = rr >> 5;      // 0=sin, 1=cos
    int j = rr & 31;         // frequency index
    double coord = d ? (double)c1 : (double)c0;
    const double sig[4] = {128.0, 16.0, 64.0, 256.0};  // band 0 = query sigma
    #pragma unroll
    for (int s = 0; s < 4; s++) {
        double step  = (log10(sig[s]) - 1.0) / 31.0;
        double omega = pow(10.0, 1.0 + (double)j * step);
        double arg   = PI_D * coord * omega;
        float val = (float)(part ? cos(arg) : sin(arg));
        float* dst = (s == 0) ? gq : (gl + (size_t)(s-1)*HW*FD);
        dst[(size_t)q*FD + f] = val;
    }
}

// ---------------- generic tiled SGEMM with fused epilogues ----------------
// C[M,N] = epi( A[M,K] @ W[K,N] ), all row-major.
// epi: (+bias[N]) (+bc[(row&16383),N]) (relu) (+af[row,N])
template<bool BIAS, bool BCAST, bool RELU, bool ADDF>
__global__ __launch_bounds__(256)
void gemm_k(const float* __restrict__ A, const float* __restrict__ W,
            const float* __restrict__ bias, const float* __restrict__ bc,
            const float* __restrict__ af, float* __restrict__ C,
            int M, int N, int K)
{
    __shared__ float As[16][128];
    __shared__ float Bs[16][128];
    int tid = threadIdx.x;
    int tx = tid & 15, ty = tid >> 4;
    long long m0 = (long long)blockIdx.y * 128;
    long long n0 = (long long)blockIdx.x * 128;

    float acc[8][8];
    #pragma unroll
    for (int i = 0; i < 8; i++)
        #pragma unroll
        for (int j = 0; j < 8; j++) acc[i][j] = 0.f;

    for (int kt = 0; kt < K; kt += 16) {
        #pragma unroll
        for (int l = 0; l < 2; l++) {
            int idx = tid + l*256;             // 0..511 float4 slots
            int ar = idx >> 2, ac4 = idx & 3;  // A tile: 128 rows x 4 f4
            float4 a = *(const float4*)(A + (m0 + ar)*(long long)K + kt + ac4*4);
            As[ac4*4+0][ar] = a.x; As[ac4*4+1][ar] = a.y;
            As[ac4*4+2][ar] = a.z; As[ac4*4+3][ar] = a.w;
            int br = idx >> 5, bc4 = idx & 31; // B tile: 16 rows x 32 f4
            *(float4*)(&Bs[br][bc4*4]) =
                *(const float4*)(W + (long long)(kt + br)*N + n0 + bc4*4);
        }
        __syncthreads();
        #pragma unroll
        for (int k = 0; k < 16; k++) {
            float ra[8], rb[8];
            *(float4*)(ra)   = *(float4*)(&As[k][ty*8]);
            *(float4*)(ra+4) = *(float4*)(&As[k][ty*8+4]);
            *(float4*)(rb)   = *(float4*)(&Bs[k][tx*8]);
            *(float4*)(rb+4) = *(float4*)(&Bs[k][tx*8+4]);
            #pragma unroll
            for (int i = 0; i < 8; i++)
                #pragma unroll
                for (int j = 0; j < 8; j++)
                    acc[i][j] += ra[i] * rb[j];
        }
        __syncthreads();
    }

    #pragma unroll
    for (int i = 0; i < 8; i++) {
        long long r  = m0 + ty*8 + i;
        long long rb_ = BCAST ? (r & 16383) : r;
        #pragma unroll
        for (int j = 0; j < 8; j += 4) {
            long long c = n0 + tx*8 + j;
            float4 v;
            v.x = acc[i][j]; v.y = acc[i][j+1]; v.z = acc[i][j+2]; v.w = acc[i][j+3];
            if (BIAS) {
                v.x += bias[c]; v.y += bias[c+1]; v.z += bias[c+2]; v.w += bias[c+3];
            }
            if (BCAST) {
                float4 bv = *(const float4*)(bc + rb_*N + c);
                v.x += bv.x; v.y += bv.y; v.z += bv.z; v.w += bv.w;
            }
            if (RELU) {
                v.x = fmaxf(v.x, 0.f); v.y = fmaxf(v.y, 0.f);
                v.z = fmaxf(v.z, 0.f); v.w = fmaxf(v.w, 0.f);
            }
            if (ADDF) {
                float4 av = *(const float4*)(af + r*N + c);
                v.x += av.x; v.y += av.y; v.z += av.z; v.w += av.w;
            }
            *(float4*)(C + r*N + c) = v;
        }
    }
}

// ---------------- fused bias: bf[i] = bo @ mod_W[i] + mod_b[i] ----------------
__global__ void bf_k(const float* __restrict__ bo, const float* __restrict__ modW,
                     const float* __restrict__ modb, float* __restrict__ bf)
{
    int i = blockIdx.x;
    int n = threadIdx.x;
    const float* Wm = modW + (size_t)i*HID*HID;
    float s = modb[i*HID + n];
    for (int k = 0; k < HID; k++) s += bo[k] * Wm[(size_t)k*HID + n];
    bf[i*HID + n] = s;
}

// ---------------- attention: online softmax, 1 thread = 1 query ----------------
__global__ __launch_bounds__(256)
void attn_k(const float* __restrict__ q, const float* __restrict__ kv,
            const float* __restrict__ tv, float* __restrict__ out)
{
    extern __shared__ float sm[];
    float* ks = sm;
    float* vs = sm + NTOK*64;
    int h = blockIdx.y, b = blockIdx.z;
    const float* kvb = kv + (size_t)b*NTOK*256;
    for (int idx = threadIdx.x; idx < NTOK*64; idx += 256) {
        int t = idx >> 6, d = idx & 63;
        ks[idx] = kvb[t*256 + h*64 + d];
        vs[idx] = kvb[t*256 + 128 + h*64 + d];
    }
    __syncthreads();

    int qi = blockIdx.x*256 + threadIdx.x;
    float qv[64], acc[64];
    const float4* qp = (const float4*)(q + (size_t)qi*FD + h*64);
    #pragma unroll
    for (int i = 0; i < 16; i++) {
        float4 t4 = qp[i];
        qv[4*i] = t4.x; qv[4*i+1] = t4.y; qv[4*i+2] = t4.z; qv[4*i+3] = t4.w;
    }
    #pragma unroll
    for (int d = 0; d < 64; d++) acc[d] = 0.f;
    float tq = tv[qi];
    float mx = -1e30f, den = 0.f;

    for (int t = 0; t < NTOK; t++) {
        const float4* k4 = (const float4*)(ks + t*64);
        float s = 0.f;
        #pragma unroll
        for (int i = 0; i < 16; i++) {
            float4 kk = k4[i];
            s += qv[4*i]*kk.x + qv[4*i+1]*kk.y + qv[4*i+2]*kk.z + qv[4*i+3]*kk.w;
        }
        float pd = tq - ((float)t + 0.5f) * (1.0f/256.0f);
        s = s*0.125f - 10.0f*pd*pd;
        const float4* v4 = (const float4*)(vs + t*64);
        if (s <= mx) {
            float p = __expf(s - mx);
            den += p;
            #pragma unroll
            for (int i = 0; i < 16; i++) {
                float4 vv = v4[i];
                acc[4*i]   += p*vv.x; acc[4*i+1] += p*vv.y;
                acc[4*i+2] += p*vv.z; acc[4*i+3] += p*vv.w;
            }
        } else {
            float cf = __expf(mx - s);
            den = den*cf + 1.0f;
            mx = s;
            #pragma unroll
            for (int i = 0; i < 16; i++) {
                float4 vv = v4[i];
                acc[4*i]   = acc[4*i]*cf   + vv.x;
                acc[4*i+1] = acc[4*i+1]*cf + vv.y;
                acc[4*i+2] = acc[4*i+2]*cf + vv.z;
                acc[4*i+3] = acc[4*i+3]*cf + vv.w;
            }
        }
    }
    float inv = 1.0f / den;
    float4* op = (float4*)(out + ((size_t)b*HW + qi)*FD + h*64);
    #pragma unroll
    for (int i = 0; i < 16; i++) {
        float4 o;
        o.x = acc[4*i]*inv; o.y = acc[4*i+1]*inv;
        o.z = acc[4*i+2]*inv; o.w = acc[4*i+3]*inv;
        op[i] = o;
    }
}

// ---------------- output projection: total = m0@W0 + hv1@W1 + hv2@W2 + Σb ----------------
__global__ __launch_bounds__(256)
void outproj_k(const float* __restrict__ m0, const float* __restrict__ hv1,
               const float* __restrict__ hv2, const float* __restrict__ outW,
               const float* __restrict__ outb, float* __restrict__ C)
{
    __shared__ float w[3*HID*3];
    for (int i = threadIdx.x; i < 3*HID*3; i += 256) w[i] = outW[i];
    __syncthreads();
    int warp = threadIdx.x >> 5, lane = threadIdx.x & 31;
    long long row = (long long)blockIdx.x*8 + warp;
    const float* srcs[3] = { m0, hv1, hv2 };
    float p0 = 0.f, p1 = 0.f, p2 = 0.f;
    #pragma unroll
    for (int s = 0; s < 3; s++) {
        const float* sp = srcs[s] + row*HID;
        const float* ws = w + s*HID*3;
        for (int k = lane*4; k < HID; k += 128) {
            float4 a = *(const float4*)(sp + k);
            p0 += a.x*ws[k*3+0] + a.y*ws[(k+1)*3+0] + a.z*ws[(k+2)*3+0] + a.w*ws[(k+3)*3+0];
            p1 += a.x*ws[k*3+1] + a.y*ws[(k+1)*3+1] + a.z*ws[(k+2)*3+1] + a.w*ws[(k+3)*3+1];
            p2 += a.x*ws[k*3+2] + a.y*ws[(k+1)*3+2] + a.z*ws[(k+2)*3+2] + a.w*ws[(k+3)*3+2];
        }
    }
    #pragma unroll
    for (int o = 16; o > 0; o >>= 1) {
        p0 += __shfl_xor_sync(0xffffffffu, p0, o);
        p1 += __shfl_xor_sync(0xffffffffu, p1, o);
        p2 += __shfl_xor_sync(0xffffffffu, p2, o);
    }
    if (lane == 0) {
        C[row*3+0] = p0 + outb[0] + outb[3] + outb[6];
        C[row*3+1] = p1 + outb[1] + outb[4] + outb[7];
        C[row*3+2] = p2 + outb[2] + outb[5] + outb[8];
    }
}

// ---------------- launch ----------------
extern "C" void kernel_launch(void* const* d_in, const int* in_sizes, int n_in,
                              void* d_out, int out_size)
{
    const float* x      = (const float*)d_in[0];
    const float* tokens = (const float*)d_in[1];
    const float* qW     = (const float*)d_in[2];
    const float* qb     = (const float*)d_in[3];
    const float* Wq     = (const float*)d_in[4];
    const float* Wkv    = (const float*)d_in[5];
    const float* Wo     = (const float*)d_in[6];
    const float* bo     = (const float*)d_in[7];
    const float* bwW    = (const float*)d_in[8];
    const float* bwb    = (const float*)d_in[9];
    const float* modW   = (const float*)d_in[10];
    const float* modb   = (const float*)d_in[11];
    const float* hvW    = (const float*)d_in[12];
    const float* hvb    = (const float*)d_in[13];
    const float* outW   = (const float*)d_in[14];
    const float* outb   = (const float*)d_in[15];
    float* total = (float*)d_out;

    float *gq, *gl, *tv, *xq, *qbuf, *kvb, *attn, *hl, *wf, *bfp, *m0b, *sb, *hv1b, *hv2b;
    cudaGetSymbolAddress((void**)&gq,   g_gammaQ);
    cudaGetSymbolAddress((void**)&gl,   g_gammaL);
    cudaGetSymbolAddress((void**)&tv,   g_tvals);
    cudaGetSymbolAddress((void**)&xq,   g_xq);
    cudaGetSymbolAddress((void**)&qbuf, g_qbuf);
    cudaGetSymbolAddress((void**)&kvb,  g_kv);
    cudaGetSymbolAddress((void**)&attn, g_attn);
    cudaGetSymbolAddress((void**)&hl,   g_hl);
    cudaGetSymbolAddress((void**)&wf,   g_wf);
    cudaGetSymbolAddress((void**)&bfp,  g_bf);
    cudaGetSymbolAddress((void**)&m0b,  g_m0);
    cudaGetSymbolAddress((void**)&sb,   g_s);
    cudaGetSymbolAddress((void**)&hv1b, g_hv1);
    cudaGetSymbolAddress((void**)&hv2b, g_hv2);

    // 1) Fourier features + t values
    gamma_k<<<HW, 128>>>(x, gq, gl, tv);

    // 2) xq = relu(gammaQ @ qW + qb)   [16384,128]x[128,512]
    gemm_k<true,false,true,false><<<dim3(4,128), 256>>>(gq, qW, qb, nullptr, nullptr, xq, HW, HID, FD);

    // 3) q = xq @ Wq                    [16384,512]x[512,128]
    gemm_k<false,false,false,false><<<dim3(1,128), 256>>>(xq, Wq, nullptr, nullptr, nullptr, qbuf, HW, FD, HID);

    // 4) kv = tokens @ Wkv              [2048,512]x[512,256]
    gemm_k<false,false,false,false><<<dim3(2,16), 256>>>(tokens, Wkv, nullptr, nullptr, nullptr, kvb, NB*NTOK, 256, HID);

    // 5) h_l[i] = relu(gammaL[i] @ bwW[i] + bwb[i])
    for (int i = 0; i < 3; i++)
        gemm_k<true,false,true,false><<<dim3(4,128), 256>>>(
            gl + (size_t)i*HW*FD, bwW + (size_t)i*FD*HID, bwb + i*HID,
            nullptr, nullptr, hl + (size_t)i*HW*HID, HW, HID, FD);

    // 6) fused weights: wf[i] = Wo @ modW[i], bf[i] = bo @ modW[i] + modb[i]
    for (int i = 0; i < 3; i++)
        gemm_k<false,false,false,false><<<dim3(4,1), 256>>>(
            Wo, modW + (size_t)i*HID*HID, nullptr, nullptr, nullptr,
            wf + (size_t)i*FD*HID, FD, HID, HID);
    bf_k<<<3, HID>>>(bo, modW, modb, bfp);

    // 7) attention
    cudaFuncSetAttribute(attn_k, cudaFuncAttributeMaxDynamicSharedMemorySize, 131072);
    attn_k<<<dim3(HW/256, 2, NB), 256, 131072>>>(qbuf, kvb, tv, attn);

    // 8) M0 = relu(attn @ wf0 + bf0 + hl0[q])
    gemm_k<true,true,true,false><<<dim3(4,1024), 256>>>(
        attn, wf, bfp, hl, nullptr, m0b, MROWS, HID, FD);

    // 9) S1 = relu(attn @ wf1 + bf1 + hl1[q]) + M0
    gemm_k<true,true,true,true><<<dim3(4,1024), 256>>>(
        attn, wf + FD*HID, bfp + HID, hl + (size_t)HW*HID, m0b, sb, MROWS, HID, FD);

    // 10) HV1 = relu(S1 @ hvW0 + hvb0)
    gemm_k<true,false,true,false><<<dim3(4,1024), 256>>>(
        sb, hvW, hvb, nullptr, nullptr, hv1b, MROWS, HID, HID);

    // 11) S2 = relu(attn @ wf2 + bf2 + hl2[q]) + HV1
    gemm_k<true,true,true,true><<<dim3(4,1024), 256>>>(
        attn, wf + 2*FD*HID, bfp + 2*HID, hl + 2ull*HW*HID, hv1b, sb, MROWS, HID, FD);

    // 12) HV2 = relu(S2 @ hvW1 + hvb1)
    gemm_k<true,false,true,false><<<dim3(4,1024), 256>>>(
        sb, hvW + (size_t)HID*HID, hvb + HID, nullptr, nullptr, hv2b, MROWS, HID, HID);

    // 13) total = m0@oW0 + hv1@oW1 + hv2@oW2 + Σ outb
    outproj_k<<<MROWS/8, 256>>>(m0b, hv1b, hv2b, outW, outb, total);
}

// round 3
// speedup vs baseline: 4.1105x; 4.1105x over previous
#include <cuda_runtime.h>
#include <cuda_fp16.h>
#include <math.h>
#include <stdint.h>

#define HW 16384
#define NB 8
#define MROWS (NB*HW)      // 131072
#define HID 512
#define FD 128
#define NTOK 256
#define PI_D 3.14159265358979323846

// ---------------- fp16 buffers ----------------
__device__ __half g_gq_h[HW*FD];
__device__ __half g_gl_h[3ull*HW*FD];
__device__ __half g_xq_h[HW*HID];
__device__ __half g_attn_h[(unsigned long long)MROWS*FD];
__device__ __half g_s_h[(unsigned long long)MROWS*HID];
__device__ __half g_tok_h[NB*NTOK*HID];
__device__ __half g_qWT[HID*FD];
__device__ __half g_WqT[FD*HID];
__device__ __half g_WkvT[256*HID];
__device__ __half g_bwWT[3*HID*FD];
__device__ __half g_modWT[3*HID*HID];
__device__ __half g_hvWT[2*HID*HID];
__device__ __half g_WoA[FD*HID];
__device__ __half g_wfT[3*HID*FD];
// ---------------- fp32 buffers ----------------
__device__ float g_tv[HW];
__device__ float g_q[HW*FD];
__device__ float g_kv[NB*NTOK*256];
__device__ float g_hl[3ull*HW*HID];
__device__ float g_bf[3*HID];
__device__ float g_m0[(unsigned long long)MROWS*HID];
__device__ float g_hv1[(unsigned long long)MROWS*HID];
__device__ float g_hv2[(unsigned long long)MROWS*HID];

// ================= helpers =================
__device__ __forceinline__ uint32_t smem_u32(const void* p) {
    uint32_t a;
    asm("{ .reg .u64 t; cvta.to.shared.u64 t, %1; cvt.u32.u64 %0, t; }" : "=r"(a) : "l"(p));
    return a;
}
__device__ __forceinline__ void ldm_x4(uint32_t* r, uint32_t addr) {
    asm volatile("ldmatrix.sync.aligned.m8n8.x4.shared.b16 {%0,%1,%2,%3}, [%4];"
                 : "=r"(r[0]), "=r"(r[1]), "=r"(r[2]), "=r"(r[3]) : "r"(addr));
}
__device__ __forceinline__ void ldm_x2(uint32_t* r, uint32_t addr) {
    asm volatile("ldmatrix.sync.aligned.m8n8.x2.shared.b16 {%0,%1}, [%2];"
                 : "=r"(r[0]), "=r"(r[1]) : "r"(addr));
}
__device__ __forceinline__ void mma16816(float* d, const uint32_t* a, const uint32_t* b) {
    asm volatile(
        "mma.sync.aligned.m16n8k16.row.col.f32.f16.f16.f32 "
        "{%0,%1,%2,%3}, {%4,%5,%6,%7}, {%8,%9}, {%0,%1,%2,%3};"
        : "+f"(d[0]), "+f"(d[1]), "+f"(d[2]), "+f"(d[3])
        : "r"(a[0]), "r"(a[1]), "r"(a[2]), "r"(a[3]), "r"(b[0]), "r"(b[1]));
}

// ================= Fourier features =================
__global__ void gamma_k(const float* __restrict__ x, __half* __restrict__ gq,
                        __half* __restrict__ gl, float* __restrict__ tv)
{
    __shared__ double omg[128];   // [band 0..3][freq 0..31]
    int q = blockIdx.x;
    int f = threadIdx.x;          // 0..127
    {
        const double sig[4] = {128.0, 16.0, 64.0, 256.0};
        int s = f >> 5, j = f & 31;
        double step = (log10(sig[s]) - 1.0) / 31.0;
        omg[f] = pow(10.0, 1.0 + (double)j * step);
    }
    __syncthreads();

    float c0 = x[2*q], c1 = x[2*q+1];
    if (f == 0) {
        int r  = (int)(c0 * 16.0f);
        int cc = (int)(c1 * 16.0f);
        tv[q] = (float)(r*16 + cc) * (1.0f/256.0f);
    }
    int d = f >> 6;
    int rr = f & 63;
    int part = rr >> 5;
    int j = rr & 31;
    double coord = d ? (double)c1 : (double)c0;
    #pragma unroll
    for (int s = 0; s < 4; s++) {
        double arg = PI_D * coord * omg[s*32 + j];
        float val = (float)(part ? cos(arg) : sin(arg));
        __half* dst = (s == 0) ? gq : (gl + (size_t)(s-1)*HW*FD);
        dst[(size_t)q*FD + f] = __float2half_rn(val);
    }
}

// ================= weight prep =================
__global__ void transpose_h_k(const float* __restrict__ in, __half* __restrict__ out,
                              int K, int N)
{
    long long i = (long long)blockIdx.x * 256 + threadIdx.x;
    long long tot = (long long)K * N;
    if (i < tot) {
        int k = (int)(i / N), n = (int)(i % N);
        out[(long long)n*K + k] = __float2half_rn(in[i]);
    }
}
__global__ void convert_h_k(const float* __restrict__ in, __half* __restrict__ out, int total)
{
    int i = blockIdx.x * 256 + threadIdx.x;
    if (i < total) out[i] = __float2half_rn(in[i]);
}

// ================= HMMA fp16 GEMM (mma.sync m16n8k16) =================
// C[M,N] = epi( A[M,K](fp16, row-major) @ WT[N,K](fp16)^T )
// epi: (+bias) (+bc[(r&16383),N]) (relu) (+af) -> Cf(fp32), Ch(fp16), CTh(fp16, [N][M])
#define LDK 72   // smem row stride in halves (64 + 8 pad); 144 bytes, 16B-aligned rows
template<bool RELU, bool BCAST, bool ADDF>
__global__ __launch_bounds__(256)
void tgemm(const __half* __restrict__ A, const __half* __restrict__ WT,
           const float* __restrict__ bias, const float* __restrict__ bc,
           const float* __restrict__ af,
           float* __restrict__ Cf, __half* __restrict__ Ch, __half* __restrict__ CTh,
           int M, int N, int K)
{
    __shared__ __half sA[128*LDK];
    __shared__ __half sB[128*LDK];
    int tid = threadIdx.x, wid = tid >> 5, lane = tid & 31;
    long long m0 = (long long)blockIdx.y * 128;
    long long n0 = (long long)blockIdx.x * 128;
    int wm = (wid >> 2) * 64;     // warp m-offset within tile
    int wn = (wid & 3) * 32;      // warp n-offset within tile

    float d[4][4][4];
    #pragma unroll
    for (int mi = 0; mi < 4; mi++)
        #pragma unroll
        for (int ni = 0; ni < 4; ni++)
            #pragma unroll
            for (int q = 0; q < 4; q++) d[mi][ni][q] = 0.f;

    uint32_t sa_u = smem_u32(sA), sb_u = smem_u32(sB);
    // ldmatrix row pointers (constant across k-tiles except kk offset)
    uint32_t a_row = (uint32_t)(lane & 15), a_koff = (uint32_t)(lane >> 4) * 8;
    uint32_t b_row = (uint32_t)(lane & 7),  b_koff = (uint32_t)((lane >> 3) & 1) * 8;

    for (int kt = 0; kt < K; kt += 64) {
        // ---- cooperative load: A tile [128][64], B tile [128][64] ----
        #pragma unroll
        for (int it = 0; it < 4; it++) {
            int idx = tid + it * 256;       // 0..1023 uint4 slots
            int r = idx >> 3, c8 = idx & 7; // row, 8-half group
            *(uint4*)(sA + r*LDK + c8*8) = *(const uint4*)(A  + (m0 + r)*(long long)K + kt + c8*8);
            *(uint4*)(sB + r*LDK + c8*8) = *(const uint4*)(WT + (n0 + r)*(long long)K + kt + c8*8);
        }
        __syncthreads();

        #pragma unroll
        for (int kk = 0; kk < 64; kk += 16) {
            uint32_t afr[4][4], bfr[4][2];
            #pragma unroll
            for (int mi = 0; mi < 4; mi++)
                ldm_x4(afr[mi], sa_u + (((uint32_t)wm + mi*16 + a_row)*LDK + kk + a_koff)*2);
            #pragma unroll
            for (int ni = 0; ni < 4; ni++)
                ldm_x2(bfr[ni], sb_u + (((uint32_t)wn + ni*8 + b_row)*LDK + kk + b_koff)*2);
            #pragma unroll
            for (int mi = 0; mi < 4; mi++)
                #pragma unroll
                for (int ni = 0; ni < 4; ni++)
                    mma16816(d[mi][ni], afr[mi], bfr[ni]);
        }
        __syncthreads();
    }

    // ---- epilogue ----
    int qr = lane >> 2;          // 0..7
    int qc = (lane & 3) * 2;     // 0,2,4,6
    #pragma unroll
    for (int mi = 0; mi < 4; mi++) {
        #pragma unroll
        for (int rh = 0; rh < 2; rh++) {
            long long r  = m0 + wm + mi*16 + rh*8 + qr;
            long long rb_ = BCAST ? (r & (HW - 1)) : r;
            #pragma unroll
            for (int ni = 0; ni < 4; ni++) {
                long long c = n0 + wn + ni*8 + qc;
                float v0 = d[mi][ni][rh*2+0];
                float v1 = d[mi][ni][rh*2+1];
                if (bias) {
                    float2 b2 = *(const float2*)(bias + c);
                    v0 += b2.x; v1 += b2.y;
                }
                if (BCAST) {
                    float2 b2 = *(const float2*)(bc + rb_*(long long)N + c);
                    v0 += b2.x; v1 += b2.y;
                }
                if (RELU) { v0 = fmaxf(v0, 0.f); v1 = fmaxf(v1, 0.f); }
                if (ADDF) {
                    float2 a2 = *(const float2*)(af + r*(long long)N + c);
                    v0 += a2.x; v1 += a2.y;
                }
                if (Cf) *(float2*)(Cf + r*(long long)N + c) = make_float2(v0, v1);
                if (Ch) {
                    __half2 h2 = __floats2half2_rn(v0, v1);
                    *(__half2*)(Ch + r*(long long)N + c) = h2;
                }
                if (CTh) {
                    CTh[c*(long long)M + r]     = __float2half_rn(v0);
                    CTh[(c+1)*(long long)M + r] = __float2half_rn(v1);
                }
            }
        }
    }
}

// ================= fused bias: bf[i] = bo @ mod_W[i] + mod_b[i] =================
__global__ void bf_k(const float* __restrict__ bo, const float* __restrict__ modW,
                     const float* __restrict__ modb, float* __restrict__ bf)
{
    int i = blockIdx.x;
    int n = threadIdx.x;
    const float* Wm = modW + (size_t)i*HID*HID;
    float s = modb[i*HID + n];
    for (int k = 0; k < HID; k++) s += bo[k] * Wm[(size_t)k*HID + n];
    bf[i*HID + n] = s;
}

// ================= attention (fp32 SIMT, fp16 output) =================
__global__ __launch_bounds__(256)
void attn_k(const float* __restrict__ q, const float* __restrict__ kv,
            const float* __restrict__ tv, __half* __restrict__ out)
{
    extern __shared__ float sm[];
    float* ks = sm;
    float* vs = sm + NTOK*64;
    int h = blockIdx.y, b = blockIdx.z;
    const float* kvb = kv + (size_t)b*NTOK*256;
    for (int idx = threadIdx.x; idx < NTOK*64; idx += 256) {
        int t = idx >> 6, d = idx & 63;
        ks[idx] = kvb[t*256 + h*64 + d];
        vs[idx] = kvb[t*256 + 128 + h*64 + d];
    }
    __syncthreads();

    int qi = blockIdx.x*256 + threadIdx.x;
    float qv[64], acc[64];
    const float4* qp = (const float4*)(q + (size_t)qi*FD + h*64);
    #pragma unroll
    for (int i = 0; i < 16; i++) {
        float4 t4 = qp[i];
        qv[4*i] = t4.x; qv[4*i+1] = t4.y; qv[4*i+2] = t4.z; qv[4*i+3] = t4.w;
    }
    #pragma unroll
    for (int d = 0; d < 64; d++) acc[d] = 0.f;
    float tq = tv[qi];
    float mx = -1e30f, den = 0.f;

    for (int t = 0; t < NTOK; t++) {
        const float4* k4 = (const float4*)(ks + t*64);
        float s = 0.f;
        #pragma unroll
        for (int i = 0; i < 16; i++) {
            float4 kk = k4[i];
            s += qv[4*i]*kk.x + qv[4*i+1]*kk.y + qv[4*i+2]*kk.z + qv[4*i+3]*kk.w;
        }
        float pd = tq - ((float)t + 0.5f) * (1.0f/256.0f);
        s = s*0.125f - 10.0f*pd*pd;
        const float4* v4 = (const float4*)(vs + t*64);
        if (s <= mx) {
            float p = __expf(s - mx);
            den += p;
            #pragma unroll
            for (int i = 0; i < 16; i++) {
                float4 vv = v4[i];
                acc[4*i]   += p*vv.x; acc[4*i+1] += p*vv.y;
                acc[4*i+2] += p*vv.z; acc[4*i+3] += p*vv.w;
            }
        } else {
            float cf = __expf(mx - s);
            den = den*cf + 1.0f;
            mx = s;
            #pragma unroll
            for (int i = 0; i < 16; i++) {
                float4 vv = v4[i];
                acc[4*i]   = acc[4*i]*cf   + vv.x;
                acc[4*i+1] = acc[4*i+1]*cf + vv.y;
                acc[4*i+2] = acc[4*i+2]*cf + vv.z;
                acc[4*i+3] = acc[4*i+3]*cf + vv.w;
            }
        }
    }
    float inv = 1.0f / den;
    __half* op = out + ((size_t)b*HW + qi)*FD + h*64;
    #pragma unroll
    for (int j = 0; j < 8; j++) {
        __half2 h0 = __floats2half2_rn(acc[8*j+0]*inv, acc[8*j+1]*inv);
        __half2 h1 = __floats2half2_rn(acc[8*j+2]*inv, acc[8*j+3]*inv);
        __half2 h2 = __floats2half2_rn(acc[8*j+4]*inv, acc[8*j+5]*inv);
        __half2 h3 = __floats2half2_rn(acc[8*j+6]*inv, acc[8*j+7]*inv);
        uint4 u;
        u.x = *(uint32_t*)&h0; u.y = *(uint32_t*)&h1;
        u.z = *(uint32_t*)&h2; u.w = *(uint32_t*)&h3;
        *(uint4*)(op + j*8) = u;
    }
}

// ================= output projection =================
__global__ __launch_bounds__(256)
void outproj_k(const float* __restrict__ m0, const float* __restrict__ hv1,
               const float* __restrict__ hv2, const float* __restrict__ outW,
               const float* __restrict__ outb, float* __restrict__ C)
{
    __shared__ float w[3*HID*3];
    for (int i = threadIdx.x; i < 3*HID*3; i += 256) w[i] = outW[i];
    __syncthreads();
    int warp = threadIdx.x >> 5, lane = threadIdx.x & 31;
    long long row = (long long)blockIdx.x*8 + warp;
    const float* srcs[3] = { m0, hv1, hv2 };
    float p0 = 0.f, p1 = 0.f, p2 = 0.f;
    #pragma unroll
    for (int s = 0; s < 3; s++) {
        const float* sp = srcs[s] + row*HID;
        const float* ws = w + s*HID*3;
        for (int k = lane*4; k < HID; k += 128) {
            float4 a = *(const float4*)(sp + k);
            p0 += a.x*ws[k*3+0] + a.y*ws[(k+1)*3+0] + a.z*ws[(k+2)*3+0] + a.w*ws[(k+3)*3+0];
            p1 += a.x*ws[k*3+1] + a.y*ws[(k+1)*3+1] + a.z*ws[(k+2)*3+1] + a.w*ws[(k+3)*3+1];
            p2 += a.x*ws[k*3+2] + a.y*ws[(k+1)*3+2] + a.z*ws[(k+2)*3+2] + a.w*ws[(k+3)*3+2];
        }
    }
    #pragma unroll
    for (int o = 16; o > 0; o >>= 1) {
        p0 += __shfl_xor_sync(0xffffffffu, p0, o);
        p1 += __shfl_xor_sync(0xffffffffu, p1, o);
        p2 += __shfl_xor_sync(0xffffffffu, p2, o);
    }
    if (lane == 0) {
        C[row*3+0] = p0 + outb[0] + outb[3] + outb[6];
        C[row*3+1] = p1 + outb[1] + outb[4] + outb[7];
        C[row*3+2] = p2 + outb[2] + outb[5] + outb[8];
    }
}

// ================= launch =================
extern "C" void kernel_launch(void* const* d_in, const int* in_sizes, int n_in,
                              void* d_out, int out_size)
{
    const float* x      = (const float*)d_in[0];
    const float* tokens = (const float*)d_in[1];
    const float* qW     = (const float*)d_in[2];
    const float* qb     = (const float*)d_in[3];
    const float* Wq     = (const float*)d_in[4];
    const float* Wkv    = (const float*)d_in[5];
    const float* Wo     = (const float*)d_in[6];
    const float* bo     = (const float*)d_in[7];
    const float* bwW    = (const float*)d_in[8];
    const float* bwb    = (const float*)d_in[9];
    const float* modW   = (const float*)d_in[10];
    const float* modb   = (const float*)d_in[11];
    const float* hvW    = (const float*)d_in[12];
    const float* hvb    = (const float*)d_in[13];
    const float* outW   = (const float*)d_in[14];
    const float* outb   = (const float*)d_in[15];
    float* total = (float*)d_out;

    __half *gqh, *glh, *xqh, *attnh, *sh, *tokh;
    __half *qWT, *WqT, *WkvT, *bwWT, *modWT, *hvWT, *WoA, *wfT;
    float *tv, *qf, *kvf, *hl, *bfp, *m0b, *hv1f, *hv2f;
    cudaGetSymbolAddress((void**)&gqh,   g_gq_h);
    cudaGetSymbolAddress((void**)&glh,   g_gl_h);
    cudaGetSymbolAddress((void**)&xqh,   g_xq_h);
    cudaGetSymbolAddress((void**)&attnh, g_attn_h);
    cudaGetSymbolAddress((void**)&sh,    g_s_h);
    cudaGetSymbolAddress((void**)&tokh,  g_tok_h);
    cudaGetSymbolAddress((void**)&qWT,   g_qWT);
    cudaGetSymbolAddress((void**)&WqT,   g_WqT);
    cudaGetSymbolAddress((void**)&WkvT,  g_WkvT);
    cudaGetSymbolAddress((void**)&bwWT,  g_bwWT);
    cudaGetSymbolAddress((void**)&modWT, g_modWT);
    cudaGetSymbolAddress((void**)&hvWT,  g_hvWT);
    cudaGetSymbolAddress((void**)&WoA,   g_WoA);
    cudaGetSymbolAddress((void**)&wfT,   g_wfT);
    cudaGetSymbolAddress((void**)&tv,    g_tv);
    cudaGetSymbolAddress((void**)&qf,    g_q);
    cudaGetSymbolAddress((void**)&kvf,   g_kv);
    cudaGetSymbolAddress((void**)&hl,    g_hl);
    cudaGetSymbolAddress((void**)&bfp,   g_bf);
    cudaGetSymbolAddress((void**)&m0b,   g_m0);
    cudaGetSymbolAddress((void**)&hv1f,  g_hv1);
    cudaGetSymbolAddress((void**)&hv2f,  g_hv2);

    cudaFuncSetAttribute(attn_k, cudaFuncAttributeMaxDynamicSharedMemorySize, 131072);

    // 1) Fourier features (fp16) + t values
    gamma_k<<<HW, 128>>>(x, gqh, glh, tv);

    // 2) weight prep: transposes + converts to fp16 [N][K]
    transpose_h_k<<<(128*512+255)/256, 256>>>(qW, qWT, 128, 512);
    transpose_h_k<<<(512*128+255)/256, 256>>>(Wq, WqT, 512, 128);
    transpose_h_k<<<(512*256+255)/256, 256>>>(Wkv, WkvT, 512, 256);
    for (int i = 0; i < 3; i++)
        transpose_h_k<<<(128*512+255)/256, 256>>>(bwW + (size_t)i*128*512, bwWT + (size_t)i*512*128, 128, 512);
    for (int i = 0; i < 3; i++)
        transpose_h_k<<<(512*512+255)/256, 256>>>(modW + (size_t)i*512*512, modWT + (size_t)i*512*512, 512, 512);
    for (int i = 0; i < 2; i++)
        transpose_h_k<<<(512*512+255)/256, 256>>>(hvW + (size_t)i*512*512, hvWT + (size_t)i*512*512, 512, 512);
    convert_h_k<<<(128*512+255)/256, 256>>>(Wo, WoA, 128*512);
    convert_h_k<<<(NB*NTOK*HID+255)/256, 256>>>(tokens, tokh, NB*NTOK*HID);

    // 3) xq = relu(gq @ qW + qb) -> fp16
    tgemm<true,false,false><<<dim3(4,128), 256>>>(
        gqh, qWT, qb, nullptr, nullptr, nullptr, xqh, nullptr, HW, HID, FD);

    // 4) q = xq @ Wq -> fp32
    tgemm<false,false,false><<<dim3(1,128), 256>>>(
        xqh, WqT, nullptr, nullptr, nullptr, qf, nullptr, nullptr, HW, FD, HID);

    // 5) kv = tokens @ Wkv -> fp32
    tgemm<false,false,false><<<dim3(2,16), 256>>>(
        tokh, WkvT, nullptr, nullptr, nullptr, kvf, nullptr, nullptr, NB*NTOK, 256, HID);

    // 6) h_l[i] = relu(gl[i] @ bwW[i] + bwb[i]) -> fp32
    for (int i = 0; i < 3; i++)
        tgemm<true,false,false><<<dim3(4,128), 256>>>(
            glh + (size_t)i*HW*FD, bwWT + (size_t)i*HID*FD, bwb + i*HID,
            nullptr, nullptr, hl + (size_t)i*HW*HID, nullptr, nullptr, HW, HID, FD);

    // 7) wfT[i] = (Wo @ modW[i])^T -> fp16 transposed [512][128]
    for (int i = 0; i < 3; i++)
        tgemm<false,false,false><<<dim3(4,1), 256>>>(
            WoA, modWT + (size_t)i*HID*HID, nullptr, nullptr, nullptr,
            nullptr, nullptr, wfT + (size_t)i*HID*FD, FD, HID, HID);
    bf_k<<<3, HID>>>(bo, modW, modb, bfp);

    // 8) attention -> fp16
    attn_k<<<dim3(HW/256, 2, NB), 256, 131072>>>(qf, kvf, tv, attnh);

    // 9) M0 = relu(attn @ wf0 + bf0 + hl0) -> fp32
    tgemm<true,true,false><<<dim3(4,1024), 256>>>(
        attnh, wfT, bfp, hl, nullptr, m0b, nullptr, nullptr, MROWS, HID, FD);

    // 10) S1 = relu(attn @ wf1 + bf1 + hl1) + M0 -> fp16
    tgemm<true,true,true><<<dim3(4,1024), 256>>>(
        attnh, wfT + HID*FD, bfp + HID, hl + (size_t)HW*HID, m0b,
        nullptr, sh, nullptr, MROWS, HID, FD);

    // 11) HV1 = relu(S1 @ hvW0 + hvb0) -> fp32
    tgemm<true,false,false><<<dim3(4,1024), 256>>>(
        sh, hvWT, hvb, nullptr, nullptr, hv1f, nullptr, nullptr, MROWS, HID, HID);

    // 12) S2 = relu(attn @ wf2 + bf2 + hl2) + HV1 -> fp16
    tgemm<true,true,true><<<dim3(4,1024), 256>>>(
        attnh, wfT + 2*HID*FD, bfp + 2*HID, hl + 2ull*HW*HID, hv1f,
        nullptr, sh, nullptr, MROWS, HID, FD);

    // 13) HV2 = relu(S2 @ hvW1 + hvb1) -> fp32
    tgemm<true,false,false><<<dim3(4,1024), 256>>>(
        sh, hvWT + (size_t)HID*HID, hvb + HID, nullptr, nullptr,
        hv2f, nullptr, nullptr, MROWS, HID, HID);

    // 14) total = m0@oW0 + hv1@oW1 + hv2@oW2 + Σb
    outproj_k<<<MROWS/8, 256>>>(m0b, hv1f, hv2f, outW, outb, total);
}

// round 4
// speedup vs baseline: 4.3400x; 1.0558x over previous
#include <cuda_runtime.h>
#include <cuda_fp16.h>
#include <math.h>
#include <stdint.h>

#define HW 16384
#define NB 8
#define MROWS (NB*HW)      // 131072
#define HID 512
#define FD 128
#define NTOK 256
#define PI_D 3.14159265358979323846

// ---------------- fp16 buffers ----------------
__device__ __half g_gq_h[HW*FD];
__device__ __half g_gl_h[3ull*HW*FD];
__device__ __half g_xq_h[HW*HID];
__device__ __half g_attn_h[(unsigned long long)MROWS*FD];
__device__ __half g_s_h[(unsigned long long)MROWS*HID];
__device__ __half g_m0_h[(unsigned long long)MROWS*HID];
__device__ __half g_hv1_h[(unsigned long long)MROWS*HID];
__device__ __half g_tok_h[NB*NTOK*HID];
__device__ __half g_qWT[HID*FD];
__device__ __half g_WqT[FD*HID];
__device__ __half g_WkvT[256*HID];
__device__ __half g_bwWT[3*HID*FD];
__device__ __half g_modWT[3*HID*HID];
__device__ __half g_hvWT[2*HID*HID];
__device__ __half g_WoA[FD*HID];
__device__ __half g_wfT[3*HID*FD];
// ---------------- fp32 buffers ----------------
__device__ float g_tv[HW];
__device__ float g_q[HW*FD];
__device__ float g_kv[NB*NTOK*256];
__device__ float g_hl[3ull*HW*HID];
__device__ float g_bf[3*HID];

// ================= helpers =================
__device__ __forceinline__ uint32_t smem_u32(const void* p) {
    uint32_t a;
    asm("{ .reg .u64 t; cvta.to.shared.u64 t, %1; cvt.u32.u64 %0, t; }" : "=r"(a) : "l"(p));
    return a;
}
__device__ __forceinline__ void ldm_x4(uint32_t* r, uint32_t addr) {
    asm volatile("ldmatrix.sync.aligned.m8n8.x4.shared.b16 {%0,%1,%2,%3}, [%4];"
                 : "=r"(r[0]), "=r"(r[1]), "=r"(r[2]), "=r"(r[3]) : "r"(addr));
}
__device__ __forceinline__ void ldm_x2(uint32_t* r, uint32_t addr) {
    asm volatile("ldmatrix.sync.aligned.m8n8.x2.shared.b16 {%0,%1}, [%2];"
                 : "=r"(r[0]), "=r"(r[1]) : "r"(addr));
}
__device__ __forceinline__ void mma16816(float* d, const uint32_t* a, const uint32_t* b) {
    asm volatile(
        "mma.sync.aligned.m16n8k16.row.col.f32.f16.f16.f32 "
        "{%0,%1,%2,%3}, {%4,%5,%6,%7}, {%8,%9}, {%0,%1,%2,%3};"
        : "+f"(d[0]), "+f"(d[1]), "+f"(d[2]), "+f"(d[3])
        : "r"(a[0]), "r"(a[1]), "r"(a[2]), "r"(a[3]), "r"(b[0]), "r"(b[1]));
}
__device__ __forceinline__ void cp16(uint32_t dst, const void* src) {
    asm volatile("cp.async.cg.shared.global [%0], [%1], 16;" :: "r"(dst), "l"(src));
}
#define CP_COMMIT() asm volatile("cp.async.commit_group;" ::: "memory")
#define CP_WAIT1()  asm volatile("cp.async.wait_group 1;" ::: "memory")
#define CP_WAIT0()  asm volatile("cp.async.wait_group 0;" ::: "memory")

// ================= Fourier features =================
__global__ void gamma_k(const float* __restrict__ x, __half* __restrict__ gq,
                        __half* __restrict__ gl, float* __restrict__ tv)
{
    __shared__ double omg[128];
    int q = blockIdx.x;
    int f = threadIdx.x;          // 0..127
    {
        const double sig[4] = {128.0, 16.0, 64.0, 256.0};
        int s = f >> 5, j = f & 31;
        double step = (log10(sig[s]) - 1.0) / 31.0;
        omg[f] = pow(10.0, 1.0 + (double)j * step);
    }
    __syncthreads();

    float c0 = x[2*q], c1 = x[2*q+1];
    if (f == 0) {
        int r  = (int)(c0 * 16.0f);
        int cc = (int)(c1 * 16.0f);
        tv[q] = (float)(r*16 + cc) * (1.0f/256.0f);
    }
    int d = f >> 6;
    int rr = f & 63;
    int part = rr >> 5;
    int j = rr & 31;
    double coord = d ? (double)c1 : (double)c0;
    #pragma unroll
    for (int s = 0; s < 4; s++) {
        double arg = PI_D * coord * omg[s*32 + j];
        float val = (float)(part ? cos(arg) : sin(arg));
        __half* dst = (s == 0) ? gq : (gl + (size_t)(s-1)*HW*FD);
        dst[(size_t)q*FD + f] = __float2half_rn(val);
    }
}

// ================= weight prep =================
__global__ void transpose_h_k(const float* __restrict__ in, __half* __restrict__ out,
                              int K, int N)
{
    long long i = (long long)blockIdx.x * 256 + threadIdx.x;
    long long tot = (long long)K * N;
    if (i < tot) {
        int k = (int)(i / N), n = (int)(i % N);
        out[(long long)n*K + k] = __float2half_rn(in[i]);
    }
}
__global__ void convert_h_k(const float* __restrict__ in, __half* __restrict__ out, int total)
{
    int i = blockIdx.x * 256 + threadIdx.x;
    if (i < total) out[i] = __float2half_rn(in[i]);
}
// total init: total[r][c] = outb[0][c]+outb[1][c]+outb[2][c]
__global__ void init_total_k(const float* __restrict__ outb, float* __restrict__ C)
{
    long long i = (long long)blockIdx.x * 256 + threadIdx.x;
    if (i < (long long)MROWS*3) {
        int c = (int)(i % 3);
        C[i] = outb[c] + outb[3+c] + outb[6+c];
    }
}

// ================= HMMA fp16 GEMM, cp.async 2-stage pipeline =================
// C[M,N] = epi( A[M,K](fp16 row-major) @ WT[N,K]^T )
// epi: (+bias) (+bc[(r&16383),N] fp32) (relu) (+af fp16) -> Cf / Ch / CTh
// OUTP: total[r][0..2] += v . outWsel[c][0..2]  (fused output projection)
#define LDK 72   // 64 + 8 pad halves; 144B rows
#define STGH (128*LDK)   // halves per matrix per stage
template<bool RELU, bool BCAST, bool ADDF, bool OUTP>
__global__ __launch_bounds__(256)
void tgemm(const __half* __restrict__ A, const __half* __restrict__ WT,
           const float* __restrict__ bias, const float* __restrict__ bc,
           const __half* __restrict__ af,
           float* __restrict__ Cf, __half* __restrict__ Ch, __half* __restrict__ CTh,
           const float* __restrict__ outWsel, float* __restrict__ total,
           int M, int N, int K)
{
    extern __shared__ __half sh_[];
    int tid = threadIdx.x, wid = tid >> 5, lane = tid & 31;
    long long m0 = (long long)blockIdx.y * 128;
    long long n0 = (long long)blockIdx.x * 128;
    int wm = (wid >> 2) * 64;
    int wn = (wid & 3) * 32;

    float d[4][4][4];
    #pragma unroll
    for (int mi = 0; mi < 4; mi++)
        #pragma unroll
        for (int ni = 0; ni < 4; ni++)
            #pragma unroll
            for (int q = 0; q < 4; q++) d[mi][ni][q] = 0.f;

    uint32_t s_u = smem_u32(sh_);
    // loader indices: 4 chunks per matrix per thread
    int lr[4], lc[4];
    #pragma unroll
    for (int it = 0; it < 4; it++) {
        int idx = tid + it*256;
        lr[it] = idx >> 3;
        lc[it] = idx & 7;
    }
    int T = K >> 6;

    // prefetch tile 0
    {
        uint32_t ba = s_u;
        uint32_t bb = s_u + STGH*2;
        #pragma unroll
        for (int it = 0; it < 4; it++) {
            cp16(ba + (lr[it]*LDK + lc[it]*8)*2, A  + (m0 + lr[it])*(long long)K + lc[it]*8);
            cp16(bb + (lr[it]*LDK + lc[it]*8)*2, WT + (n0 + lr[it])*(long long)K + lc[it]*8);
        }
        CP_COMMIT();
    }

    uint32_t a_row = (uint32_t)(lane & 15), a_koff = (uint32_t)(lane >> 4) * 8;
    uint32_t b_row = (uint32_t)(lane & 7),  b_koff = (uint32_t)((lane >> 3) & 1) * 8;

    for (int t = 0; t < T; t++) {
        if (t + 1 < T) {
            int kt = (t+1) << 6;
            uint32_t ba = s_u + ((t+1) & 1) * (2*STGH*2);
            uint32_t bb = ba + STGH*2;
            #pragma unroll
            for (int it = 0; it < 4; it++) {
                cp16(ba + (lr[it]*LDK + lc[it]*8)*2, A  + (m0 + lr[it])*(long long)K + kt + lc[it]*8);
                cp16(bb + (lr[it]*LDK + lc[it]*8)*2, WT + (n0 + lr[it])*(long long)K + kt + lc[it]*8);
            }
            CP_COMMIT();
            CP_WAIT1();
        } else {
            CP_WAIT0();
        }
        __syncthreads();

        uint32_t sa_u = s_u + (t & 1) * (2*STGH*2);
        uint32_t sb_u = sa_u + STGH*2;
        #pragma unroll
        for (int kk = 0; kk < 64; kk += 16) {
            uint32_t afr[4][4], bfr[4][2];
            #pragma unroll
            for (int mi = 0; mi < 4; mi++)
                ldm_x4(afr[mi], sa_u + (((uint32_t)wm + mi*16 + a_row)*LDK + kk + a_koff)*2);
            #pragma unroll
            for (int ni = 0; ni < 4; ni++)
                ldm_x2(bfr[ni], sb_u + (((uint32_t)wn + ni*8 + b_row)*LDK + kk + b_koff)*2);
            #pragma unroll
            for (int mi = 0; mi < 4; mi++)
                #pragma unroll
                for (int ni = 0; ni < 4; ni++)
                    mma16816(d[mi][ni], afr[mi], bfr[ni]);
        }
        __syncthreads();
    }

    // ---- reduction buffer for fused outproj (reuse stage smem) ----
    float* red = (float*)sh_;
    if (OUTP) {
        for (int i = tid; i < 128*3; i += 256) red[i] = 0.f;
        __syncthreads();
    }

    // ---- epilogue ----
    int qr = lane >> 2;
    int qc = (lane & 3) * 2;
    #pragma unroll
    for (int mi = 0; mi < 4; mi++) {
        #pragma unroll
        for (int rh = 0; rh < 2; rh++) {
            int rloc = wm + mi*16 + rh*8 + qr;
            long long r  = m0 + rloc;
            long long rb_ = BCAST ? (r & (HW - 1)) : r;
            float p0 = 0.f, p1 = 0.f, p2 = 0.f;
            #pragma unroll
            for (int ni = 0; ni < 4; ni++) {
                long long c = n0 + wn + ni*8 + qc;
                float v0 = d[mi][ni][rh*2+0];
                float v1 = d[mi][ni][rh*2+1];
                if (bias) {
                    float2 b2 = *(const float2*)(bias + c);
                    v0 += b2.x; v1 += b2.y;
                }
                if (BCAST) {
                    float2 b2 = *(const float2*)(bc + rb_*(long long)N + c);
                    v0 += b2.x; v1 += b2.y;
                }
                if (RELU) { v0 = fmaxf(v0, 0.f); v1 = fmaxf(v1, 0.f); }
                if (ADDF) {
                    __half2 a2 = *(const __half2*)(af + r*(long long)N + c);
                    float2 af2 = __half22float2(a2);
                    v0 += af2.x; v1 += af2.y;
                }
                if (Cf) *(float2*)(Cf + r*(long long)N + c) = make_float2(v0, v1);
                if (Ch) *(__half2*)(Ch + r*(long long)N + c) = __floats2half2_rn(v0, v1);
                if (CTh) {
                    CTh[c*(long long)M + r]     = __float2half_rn(v0);
                    CTh[(c+1)*(long long)M + r] = __float2half_rn(v1);
                }
                if (OUTP) {
                    const float* w0 = outWsel + c*3;
                    p0 += v0*w0[0] + v1*w0[3];
                    p1 += v0*w0[1] + v1*w0[4];
                    p2 += v0*w0[2] + v1*w0[5];
                }
            }
            if (OUTP) {
                // reduce over the 4 lanes sharing this row (lane bits 0-1)
                #pragma unroll
                for (int o = 1; o < 4; o <<= 1) {
                    p0 += __shfl_xor_sync(0xffffffffu, p0, o);
                    p1 += __shfl_xor_sync(0xffffffffu, p1, o);
                    p2 += __shfl_xor_sync(0xffffffffu, p2, o);
                }
                if ((lane & 3) == 0) {
                    atomicAdd(&red[rloc*3+0], p0);
                    atomicAdd(&red[rloc*3+1], p1);
                    atomicAdd(&red[rloc*3+2], p2);
                }
            }
        }
    }
    if (OUTP) {
        __syncthreads();
        for (int i = tid; i < 128*3; i += 256)
            atomicAdd(&total[(m0 + (i/3))*3 + (i%3)], red[i]);
    }
}

// ================= fused bias: bf[i] = bo @ mod_W[i] + mod_b[i] =================
__global__ void bf_k(const float* __restrict__ bo, const float* __restrict__ modW,
                     const float* __restrict__ modb, float* __restrict__ bf)
{
    int i = blockIdx.x;
    int n = threadIdx.x;
    const float* Wm = modW + (size_t)i*HID*HID;
    float s = modb[i*HID + n];
    for (int k = 0; k < HID; k++) s += bo[k] * Wm[(size_t)k*HID + n];
    bf[i*HID + n] = s;
}

// ================= attention (fp32 SIMT, fp16 output) =================
__global__ __launch_bounds__(256)
void attn_k(const float* __restrict__ q, const float* __restrict__ kv,
            const float* __restrict__ tv, __half* __restrict__ out)
{
    extern __shared__ float sm[];
    float* ks = sm;
    float* vs = sm + NTOK*64;
    int h = blockIdx.y, b = blockIdx.z;
    const float* kvb = kv + (size_t)b*NTOK*256;
    for (int idx = threadIdx.x; idx < NTOK*64; idx += 256) {
        int t = idx >> 6, d = idx & 63;
        ks[idx] = kvb[t*256 + h*64 + d];
        vs[idx] = kvb[t*256 + 128 + h*64 + d];
    }
    __syncthreads();

    int qi = blockIdx.x*256 + threadIdx.x;
    float qv[64], acc[64];
    const float4* qp = (const float4*)(q + (size_t)qi*FD + h*64);
    #pragma unroll
    for (int i = 0; i < 16; i++) {
        float4 t4 = qp[i];
        qv[4*i] = t4.x; qv[4*i+1] = t4.y; qv[4*i+2] = t4.z; qv[4*i+3] = t4.w;
    }
    #pragma unroll
    for (int d = 0; d < 64; d++) acc[d] = 0.f;
    float tq = tv[qi];
    float mx = -1e30f, den = 0.f;

    for (int t = 0; t < NTOK; t++) {
        const float4* k4 = (const float4*)(ks + t*64);
        float s = 0.f;
        #pragma unroll
        for (int i = 0; i < 16; i++) {
            float4 kk = k4[i];
            s += qv[4*i]*kk.x + qv[4*i+1]*kk.y + qv[4*i+2]*kk.z + qv[4*i+3]*kk.w;
        }
        float pd = tq - ((float)t + 0.5f) * (1.0f/256.0f);
        s = s*0.125f - 10.0f*pd*pd;
        const float4* v4 = (const float4*)(vs + t*64);
        if (s <= mx) {
            float p = __expf(s - mx);
            den += p;
            #pragma unroll
            for (int i = 0; i < 16; i++) {
                float4 vv = v4[i];
                acc[4*i]   += p*vv.x; acc[4*i+1] += p*vv.y;
                acc[4*i+2] += p*vv.z; acc[4*i+3] += p*vv.w;
            }
        } else {
            float cf = __expf(mx - s);
            den = den*cf + 1.0f;
            mx = s;
            #pragma unroll
            for (int i = 0; i < 16; i++) {
                float4 vv = v4[i];
                acc[4*i]   = acc[4*i]*cf   + vv.x;
                acc[4*i+1] = acc[4*i+1]*cf + vv.y;
                acc[4*i+2] = acc[4*i+2]*cf + vv.z;
                acc[4*i+3] = acc[4*i+3]*cf + vv.w;
            }
        }
    }
    float inv = 1.0f / den;
    __half* op = out + ((size_t)b*HW + qi)*FD + h*64;
    #pragma unroll
    for (int j = 0; j < 8; j++) {
        __half2 h0 = __floats2half2_rn(acc[8*j+0]*inv, acc[8*j+1]*inv);
        __half2 h1 = __floats2half2_rn(acc[8*j+2]*inv, acc[8*j+3]*inv);
        __half2 h2 = __floats2half2_rn(acc[8*j+4]*inv, acc[8*j+5]*inv);
        __half2 h3 = __floats2half2_rn(acc[8*j+6]*inv, acc[8*j+7]*inv);
        uint4 u;
        u.x = *(uint32_t*)&h0; u.y = *(uint32_t*)&h1;
        u.z = *(uint32_t*)&h2; u.w = *(uint32_t*)&h3;
        *(uint4*)(op + j*8) = u;
    }
}

// ================= launch =================
#define TG_SMEM (4*STGH*2)   // 73728 bytes

extern "C" void kernel_launch(void* const* d_in, const int* in_sizes, int n_in,
                              void* d_out, int out_size)
{
    const float* x      = (const float*)d_in[0];
    const float* tokens = (const float*)d_in[1];
    const float* qW     = (const float*)d_in[2];
    const float* qb     = (const float*)d_in[3];
    const float* Wq     = (const float*)d_in[4];
    const float* Wkv    = (const float*)d_in[5];
    const float* Wo     = (const float*)d_in[6];
    const float* bo     = (const float*)d_in[7];
    const float* bwW    = (const float*)d_in[8];
    const float* bwb    = (const float*)d_in[9];
    const float* modW   = (const float*)d_in[10];
    const float* modb   = (const float*)d_in[11];
    const float* hvW    = (const float*)d_in[12];
    const float* hvb    = (const float*)d_in[13];
    const float* outW   = (const float*)d_in[14];
    const float* outb   = (const float*)d_in[15];
    float* total = (float*)d_out;

    __half *gqh, *glh, *xqh, *attnh, *sh, *m0h, *hv1h, *tokh;
    __half *qWT, *WqT, *WkvT, *bwWT, *modWT, *hvWT, *WoA, *wfT;
    float *tv, *qf, *kvf, *hl, *bfp;
    cudaGetSymbolAddress((void**)&gqh,   g_gq_h);
    cudaGetSymbolAddress((void**)&glh,   g_gl_h);
    cudaGetSymbolAddress((void**)&xqh,   g_xq_h);
    cudaGetSymbolAddress((void**)&attnh, g_attn_h);
    cudaGetSymbolAddress((void**)&sh,    g_s_h);
    cudaGetSymbolAddress((void**)&m0h,   g_m0_h);
    cudaGetSymbolAddress((void**)&hv1h,  g_hv1_h);
    cudaGetSymbolAddress((void**)&tokh,  g_tok_h);
    cudaGetSymbolAddress((void**)&qWT,   g_qWT);
    cudaGetSymbolAddress((void**)&WqT,   g_WqT);
    cudaGetSymbolAddress((void**)&WkvT,  g_WkvT);
    cudaGetSymbolAddress((void**)&bwWT,  g_bwWT);
    cudaGetSymbolAddress((void**)&modWT, g_modWT);
    cudaGetSymbolAddress((void**)&hvWT,  g_hvWT);
    cudaGetSymbolAddress((void**)&WoA,   g_WoA);
    cudaGetSymbolAddress((void**)&wfT,   g_wfT);
    cudaGetSymbolAddress((void**)&tv,    g_tv);
    cudaGetSymbolAddress((void**)&qf,    g_q);
    cudaGetSymbolAddress((void**)&kvf,   g_kv);
    cudaGetSymbolAddress((void**)&hl,    g_hl);
    cudaGetSymbolAddress((void**)&bfp,   g_bf);

    cudaFuncSetAttribute(tgemm<false,false,false,false>, cudaFuncAttributeMaxDynamicSharedMemorySize, TG_SMEM);
    cudaFuncSetAttribute(tgemm<true,false,false,false>,  cudaFuncAttributeMaxDynamicSharedMemorySize, TG_SMEM);
    cudaFuncSetAttribute(tgemm<true,true,false,true>,    cudaFuncAttributeMaxDynamicSharedMemorySize, TG_SMEM);
    cudaFuncSetAttribute(tgemm<true,true,true,false>,    cudaFuncAttributeMaxDynamicSharedMemorySize, TG_SMEM);
    cudaFuncSetAttribute(tgemm<true,false,false,true>,   cudaFuncAttributeMaxDynamicSharedMemorySize, TG_SMEM);
    cudaFuncSetAttribute(attn_k, cudaFuncAttributeMaxDynamicSharedMemorySize, 131072);

    // 1) Fourier features + t values
    gamma_k<<<HW, 128>>>(x, gqh, glh, tv);

    // 2) weight prep
    transpose_h_k<<<(128*512+255)/256, 256>>>(qW, qWT, 128, 512);
    transpose_h_k<<<(512*128+255)/256, 256>>>(Wq, WqT, 512, 128);
    transpose_h_k<<<(512*256+255)/256, 256>>>(Wkv, WkvT, 512, 256);
    for (int i = 0; i < 3; i++)
        transpose_h_k<<<(128*512+255)/256, 256>>>(bwW + (size_t)i*128*512, bwWT + (size_t)i*512*128, 128, 512);
    for (int i = 0; i < 3; i++)
        transpose_h_k<<<(512*512+255)/256, 256>>>(modW + (size_t)i*512*512, modWT + (size_t)i*512*512, 512, 512);
    for (int i = 0; i < 2; i++)
        transpose_h_k<<<(512*512+255)/256, 256>>>(hvW + (size_t)i*512*512, hvWT + (size_t)i*512*512, 512, 512);
    convert_h_k<<<(128*512+255)/256, 256>>>(Wo, WoA, 128*512);
    convert_h_k<<<(NB*NTOK*HID+255)/256, 256>>>(tokens, tokh, NB*NTOK*HID);
    init_total_k<<<(MROWS*3+255)/256, 256>>>(outb, total);

    // 3) xq = relu(gq @ qW + qb) -> fp16
    tgemm<true,false,false,false><<<dim3(4,128), 256, TG_SMEM>>>(
        gqh, qWT, qb, nullptr, nullptr, nullptr, xqh, nullptr, nullptr, nullptr, HW, HID, FD);

    // 4) q = xq @ Wq -> fp32
    tgemm<false,false,false,false><<<dim3(1,128), 256, TG_SMEM>>>(
        xqh, WqT, nullptr, nullptr, nullptr, qf, nullptr, nullptr, nullptr, nullptr, HW, FD, HID);

    // 5) kv = tokens @ Wkv -> fp32
    tgemm<false,false,false,false><<<dim3(2,16), 256, TG_SMEM>>>(
        tokh, WkvT, nullptr, nullptr, nullptr, kvf, nullptr, nullptr, nullptr, nullptr, NB*NTOK, 256, HID);

    // 6) h_l[i] = relu(gl[i] @ bwW[i] + bwb[i]) -> fp32
    for (int i = 0; i < 3; i++)
        tgemm<true,false,false,false><<<dim3(4,128), 256, TG_SMEM>>>(
            glh + (size_t)i*HW*FD, bwWT + (size_t)i*HID*FD, bwb + i*HID,
            nullptr, nullptr, hl + (size_t)i*HW*HID, nullptr, nullptr, nullptr, nullptr, HW, HID, FD);

    // 7) wfT[i] = (Wo @ modW[i])^T -> fp16 [512][128]
    for (int i = 0; i < 3; i++)
        tgemm<false,false,false,false><<<dim3(4,1), 256, TG_SMEM>>>(
            WoA, modWT + (size_t)i*HID*HID, nullptr, nullptr, nullptr,
            nullptr, nullptr, wfT + (size_t)i*HID*FD, nullptr, nullptr, FD, HID, HID);
    bf_k<<<3, HID>>>(bo, modW, modb, bfp);

    // 8) attention -> fp16
    attn_k<<<dim3(HW/256, 2, NB), 256, 131072>>>(qf, kvf, tv, attnh);

    // 9) M0 = relu(attn @ wf0 + bf0 + hl0) -> fp16 m0h ; total += M0 @ outW0
    tgemm<true,true,false,true><<<dim3(4,1024), 256, TG_SMEM>>>(
        attnh, wfT, bfp, hl, nullptr, nullptr, m0h, nullptr, outW, total, MROWS, HID, FD);

    // 10) S1 = relu(attn @ wf1 + bf1 + hl1) + m0 -> fp16
    tgemm<true,true,true,false><<<dim3(4,1024), 256, TG_SMEM>>>(
        attnh, wfT + HID*FD, bfp + HID, hl + (size_t)HW*HID, m0h,
        nullptr, sh, nullptr, nullptr, nullptr, MROWS, HID, FD);

    // 11) HV1 = relu(S1 @ hvW0 + hvb0) -> fp16 ; total += HV1 @ outW1
    tgemm<true,false,false,true><<<dim3(4,1024), 256, TG_SMEM>>>(
        sh, hvWT, hvb, nullptr, nullptr, nullptr, hv1h, nullptr,
        outW + 512*3, total, MROWS, HID, HID);

    // 12) S2 = relu(attn @ wf2 + bf2 + hl2) + hv1 -> fp16
    tgemm<true,true,true,false><<<dim3(4,1024), 256, TG_SMEM>>>(
        attnh, wfT + 2*HID*FD, bfp + 2*HID, hl + 2ull*HW*HID, hv1h,
        nullptr, sh, nullptr, nullptr, nullptr, MROWS, HID, FD);

    // 13) HV2 = relu(S2 @ hvW1 + hvb1) ; total += HV2 @ outW2 (no buffer write)
    tgemm<true,false,false,true><<<dim3(4,1024), 256, TG_SMEM>>>(
        sh, hvWT + (size_t)HID*HID, hvb + HID, nullptr, nullptr, nullptr,
        nullptr, nullptr, outW + 2*512*3, total, MROWS, HID, HID);
}

// round 5
// speedup vs baseline: 5.3370x; 1.2297x over previous
#include <cuda_runtime.h>
#include <cuda_fp16.h>
#include <math.h>
#include <stdint.h>

#define HW 16384
#define NB 8
#define MROWS (NB*HW)      // 131072
#define HID 512
#define FD 128
#define NTOK 256
#define PI_D 3.14159265358979323846

// ---------------- fp16 buffers ----------------
__device__ __half g_gq_h[HW*FD];
__device__ __half g_gl_h[3ull*HW*FD];
__device__ __half g_xq_h[HW*HID];
__device__ __half g_q_h[HW*FD];
__device__ __half g_kv_h[NB*NTOK*256];
__device__ __half g_attn_h[(unsigned long long)MROWS*FD];
__device__ __half g_s_h[(unsigned long long)MROWS*HID];
__device__ __half g_m0_h[(unsigned long long)MROWS*HID];
__device__ __half g_hv1_h[(unsigned long long)MROWS*HID];
__device__ __half g_tok_h[NB*NTOK*HID];
__device__ __half g_qWT[HID*FD];
__device__ __half g_WqT[FD*HID];
__device__ __half g_WkvT[256*HID];
__device__ __half g_bwWT[3*HID*FD];
__device__ __half g_modWT[3*HID*HID];
__device__ __half g_hvWT[2*HID*HID];
__device__ __half g_WoA[FD*HID];
__device__ __half g_wfT[3*HID*FD];
// ---------------- fp32 buffers ----------------
__device__ float g_tv[HW];
__device__ float g_hl[3ull*HW*HID];
__device__ float g_bf[3*HID];

// ================= helpers =================
__device__ __forceinline__ uint32_t smem_u32(const void* p) {
    uint32_t a;
    asm("{ .reg .u64 t; cvta.to.shared.u64 t, %1; cvt.u32.u64 %0, t; }" : "=r"(a) : "l"(p));
    return a;
}
__device__ __forceinline__ void ldm_x4(uint32_t* r, uint32_t addr) {
    asm volatile("ldmatrix.sync.aligned.m8n8.x4.shared.b16 {%0,%1,%2,%3}, [%4];"
                 : "=r"(r[0]), "=r"(r[1]), "=r"(r[2]), "=r"(r[3]) : "r"(addr));
}
__device__ __forceinline__ void ldm_x2(uint32_t* r, uint32_t addr) {
    asm volatile("ldmatrix.sync.aligned.m8n8.x2.shared.b16 {%0,%1}, [%2];"
                 : "=r"(r[0]), "=r"(r[1]) : "r"(addr));
}
__device__ __forceinline__ void mma16816(float* d, const uint32_t* a, const uint32_t* b) {
    asm volatile(
        "mma.sync.aligned.m16n8k16.row.col.f32.f16.f16.f32 "
        "{%0,%1,%2,%3}, {%4,%5,%6,%7}, {%8,%9}, {%0,%1,%2,%3};"
        : "+f"(d[0]), "+f"(d[1]), "+f"(d[2]), "+f"(d[3])
        : "r"(a[0]), "r"(a[1]), "r"(a[2]), "r"(a[3]), "r"(b[0]), "r"(b[1]));
}
__device__ __forceinline__ void cp16(uint32_t dst, const void* src) {
    asm volatile("cp.async.cg.shared.global [%0], [%1], 16;" :: "r"(dst), "l"(src));
}
#define CP_COMMIT() asm volatile("cp.async.commit_group;" ::: "memory")
#define CP_WAIT1()  asm volatile("cp.async.wait_group 1;" ::: "memory")
#define CP_WAIT0()  asm volatile("cp.async.wait_group 0;" ::: "memory")

// ================= Fourier features =================
__global__ void gamma_k(const float* __restrict__ x, __half* __restrict__ gq,
                        __half* __restrict__ gl, float* __restrict__ tv)
{
    __shared__ double omg[128];
    int q = blockIdx.x;
    int f = threadIdx.x;
    {
        const double sig[4] = {128.0, 16.0, 64.0, 256.0};
        int s = f >> 5, j = f & 31;
        double step = (log10(sig[s]) - 1.0) / 31.0;
        omg[f] = pow(10.0, 1.0 + (double)j * step);
    }
    __syncthreads();

    float c0 = x[2*q], c1 = x[2*q+1];
    if (f == 0) {
        int r  = (int)(c0 * 16.0f);
        int cc = (int)(c1 * 16.0f);
        tv[q] = (float)(r*16 + cc) * (1.0f/256.0f);
    }
    int d = f >> 6;
    int rr = f & 63;
    int part = rr >> 5;
    int j = rr & 31;
    double coord = d ? (double)c1 : (double)c0;
    #pragma unroll
    for (int s = 0; s < 4; s++) {
        double arg = PI_D * coord * omg[s*32 + j];
        float val = (float)(part ? cos(arg) : sin(arg));
        __half* dst = (s == 0) ? gq : (gl + (size_t)(s-1)*HW*FD);
        dst[(size_t)q*FD + f] = __float2half_rn(val);
    }
}

// ================= weight prep =================
__global__ void transpose_h_k(const float* __restrict__ in, __half* __restrict__ out,
                              int K, int N)
{
    long long i = (long long)blockIdx.x * 256 + threadIdx.x;
    long long tot = (long long)K * N;
    if (i < tot) {
        int k = (int)(i / N), n = (int)(i % N);
        out[(long long)n*K + k] = __float2half_rn(in[i]);
    }
}
__global__ void convert_h_k(const float* __restrict__ in, __half* __restrict__ out, int total)
{
    int i = blockIdx.x * 256 + threadIdx.x;
    if (i < total) out[i] = __float2half_rn(in[i]);
}
__global__ void init_total_k(const float* __restrict__ outb, float* __restrict__ C)
{
    long long i = (long long)blockIdx.x * 256 + threadIdx.x;
    if (i < (long long)MROWS*3) {
        int c = (int)(i % 3);
        C[i] = outb[c] + outb[3+c] + outb[6+c];
    }
}

// ================= HMMA fp16 GEMM, cp.async 2-stage pipeline =================
#define LDK 72
#define STGH (128*LDK)
template<bool RELU, bool BCAST, bool ADDF, bool OUTP>
__global__ __launch_bounds__(256)
void tgemm(const __half* __restrict__ A, const __half* __restrict__ WT,
           const float* __restrict__ bias, const float* __restrict__ bc,
           const __half* __restrict__ af,
           float* __restrict__ Cf, __half* __restrict__ Ch, __half* __restrict__ CTh,
           const float* __restrict__ outWsel, float* __restrict__ total,
           int M, int N, int K)
{
    extern __shared__ __half sh_[];
    int tid = threadIdx.x, wid = tid >> 5, lane = tid & 31;
    long long m0 = (long long)blockIdx.y * 128;
    long long n0 = (long long)blockIdx.x * 128;
    int wm = (wid >> 2) * 64;
    int wn = (wid & 3) * 32;

    float d[4][4][4];
    #pragma unroll
    for (int mi = 0; mi < 4; mi++)
        #pragma unroll
        for (int ni = 0; ni < 4; ni++)
            #pragma unroll
            for (int q = 0; q < 4; q++) d[mi][ni][q] = 0.f;

    uint32_t s_u = smem_u32(sh_);
    int lr[4], lc[4];
    #pragma unroll
    for (int it = 0; it < 4; it++) {
        int idx = tid + it*256;
        lr[it] = idx >> 3;
        lc[it] = idx & 7;
    }
    int T = K >> 6;

    {
        uint32_t ba = s_u;
        uint32_t bb = s_u + STGH*2;
        #pragma unroll
        for (int it = 0; it < 4; it++) {
            cp16(ba + (lr[it]*LDK + lc[it]*8)*2, A  + (m0 + lr[it])*(long long)K + lc[it]*8);
            cp16(bb + (lr[it]*LDK + lc[it]*8)*2, WT + (n0 + lr[it])*(long long)K + lc[it]*8);
        }
        CP_COMMIT();
    }

    uint32_t a_row = (uint32_t)(lane & 15), a_koff = (uint32_t)(lane >> 4) * 8;
    uint32_t b_row = (uint32_t)(lane & 7),  b_koff = (uint32_t)((lane >> 3) & 1) * 8;

    for (int t = 0; t < T; t++) {
        if (t + 1 < T) {
            int kt = (t+1) << 6;
            uint32_t ba = s_u + ((t+1) & 1) * (2*STGH*2);
            uint32_t bb = ba + STGH*2;
            #pragma unroll
            for (int it = 0; it < 4; it++) {
                cp16(ba + (lr[it]*LDK + lc[it]*8)*2, A  + (m0 + lr[it])*(long long)K + kt + lc[it]*8);
                cp16(bb + (lr[it]*LDK + lc[it]*8)*2, WT + (n0 + lr[it])*(long long)K + kt + lc[it]*8);
            }
            CP_COMMIT();
            CP_WAIT1();
        } else {
            CP_WAIT0();
        }
        __syncthreads();

        uint32_t sa_u = s_u + (t & 1) * (2*STGH*2);
        uint32_t sb_u = sa_u + STGH*2;
        #pragma unroll
        for (int kk = 0; kk < 64; kk += 16) {
            uint32_t afr[4][4], bfr[4][2];
            #pragma unroll
            for (int mi = 0; mi < 4; mi++)
                ldm_x4(afr[mi], sa_u + (((uint32_t)wm + mi*16 + a_row)*LDK + kk + a_koff)*2);
            #pragma unroll
            for (int ni = 0; ni < 4; ni++)
                ldm_x2(bfr[ni], sb_u + (((uint32_t)wn + ni*8 + b_row)*LDK + kk + b_koff)*2);
            #pragma unroll
            for (int mi = 0; mi < 4; mi++)
                #pragma unroll
                for (int ni = 0; ni < 4; ni++)
                    mma16816(d[mi][ni], afr[mi], bfr[ni]);
        }
        __syncthreads();
    }

    float* red = (float*)sh_;
    if (OUTP) {
        for (int i = tid; i < 128*3; i += 256) red[i] = 0.f;
        __syncthreads();
    }

    int qr = lane >> 2;
    int qc = (lane & 3) * 2;
    #pragma unroll
    for (int mi = 0; mi < 4; mi++) {
        #pragma unroll
        for (int rh = 0; rh < 2; rh++) {
            int rloc = wm + mi*16 + rh*8 + qr;
            long long r  = m0 + rloc;
            long long rb_ = BCAST ? (r & (HW - 1)) : r;
            float p0 = 0.f, p1 = 0.f, p2 = 0.f;
            #pragma unroll
            for (int ni = 0; ni < 4; ni++) {
                long long c = n0 + wn + ni*8 + qc;
                float v0 = d[mi][ni][rh*2+0];
                float v1 = d[mi][ni][rh*2+1];
                if (bias) {
                    float2 b2 = *(const float2*)(bias + c);
                    v0 += b2.x; v1 += b2.y;
                }
                if (BCAST) {
                    float2 b2 = *(const float2*)(bc + rb_*(long long)N + c);
                    v0 += b2.x; v1 += b2.y;
                }
                if (RELU) { v0 = fmaxf(v0, 0.f); v1 = fmaxf(v1, 0.f); }
                if (ADDF) {
                    __half2 a2 = *(const __half2*)(af + r*(long long)N + c);
                    float2 af2 = __half22float2(a2);
                    v0 += af2.x; v1 += af2.y;
                }
                if (Cf) *(float2*)(Cf + r*(long long)N + c) = make_float2(v0, v1);
                if (Ch) *(__half2*)(Ch + r*(long long)N + c) = __floats2half2_rn(v0, v1);
                if (CTh) {
                    CTh[c*(long long)M + r]     = __float2half_rn(v0);
                    CTh[(c+1)*(long long)M + r] = __float2half_rn(v1);
                }
                if (OUTP) {
                    const float* w0 = outWsel + c*3;
                    p0 += v0*w0[0] + v1*w0[3];
                    p1 += v0*w0[1] + v1*w0[4];
                    p2 += v0*w0[2] + v1*w0[5];
                }
            }
            if (OUTP) {
                #pragma unroll
                for (int o = 1; o < 4; o <<= 1) {
                    p0 += __shfl_xor_sync(0xffffffffu, p0, o);
                    p1 += __shfl_xor_sync(0xffffffffu, p1, o);
                    p2 += __shfl_xor_sync(0xffffffffu, p2, o);
                }
                if ((lane & 3) == 0) {
                    atomicAdd(&red[rloc*3+0], p0);
                    atomicAdd(&red[rloc*3+1], p1);
                    atomicAdd(&red[rloc*3+2], p2);
                }
            }
        }
    }
    if (OUTP) {
        __syncthreads();
        for (int i = tid; i < 128*3; i += 256)
            atomicAdd(&total[(m0 + (i/3))*3 + (i%3)], red[i]);
    }
}

// ================= fused bias: bf[i] = bo @ mod_W[i] + mod_b[i] =================
__global__ void bf_k(const float* __restrict__ bo, const float* __restrict__ modW,
                     const float* __restrict__ modb, float* __restrict__ bf)
{
    int i = blockIdx.x;
    int n = threadIdx.x;
    const float* Wm = modW + (size_t)i*HID*HID;
    float s = modb[i*HID + n];
    for (int k = 0; k < HID; k++) s += bo[k] * Wm[(size_t)k*HID + n];
    bf[i*HID + n] = s;
}

// ================= HMMA attention =================
// CTA: 128 queries x one (b,h). S = Q K^T (+bias) -> softmax -> O = P V.
#define AT_QSTR 72
#define AT_KSTR 72
#define AT_VSTR 264
#define AT_PSTR 264
#define AT_SMEM ((128*AT_QSTR + 256*AT_KSTR + 64*AT_VSTR + 128*AT_PSTR)*2)
__global__ __launch_bounds__(256)
void attn_mma_k(const __half* __restrict__ qh, const __half* __restrict__ kvh,
                const float* __restrict__ tv, __half* __restrict__ out)
{
    extern __shared__ __half sm[];
    __half* sQ = sm;
    __half* sK = sQ + 128*AT_QSTR;
    __half* sV = sK + 256*AT_KSTR;   // V transposed: [64 dim][256 tok]
    __half* sP = sV + 64*AT_VSTR;
    int tid = threadIdx.x, wid = tid >> 5, lane = tid & 31;
    int h = blockIdx.y, b = blockIdx.z;
    long long q0 = (long long)blockIdx.x * 128;
    const __half* kvb = kvh + (size_t)b*NTOK*256;

    // load Q [128][64]
    for (int idx = tid; idx < 1024; idx += 256) {
        int r = idx >> 3, c8 = idx & 7;
        *(uint4*)(sQ + r*AT_QSTR + c8*8) = *(const uint4*)(qh + (q0 + r)*FD + h*64 + c8*8);
    }
    // load K [256][64]
    for (int idx = tid; idx < 2048; idx += 256) {
        int t = idx >> 3, c8 = idx & 7;
        *(uint4*)(sK + t*AT_KSTR + c8*8) = *(const uint4*)(kvb + t*256 + h*64 + c8*8);
    }
    // load V transposed
    for (int idx = tid; idx < NTOK*64; idx += 256) {
        int t = idx >> 6, dd = idx & 63;
        sV[dd*AT_VSTR + t] = kvb[t*256 + 128 + h*64 + dd];
    }
    __syncthreads();

    uint32_t sQu = smem_u32(sQ), sKu = smem_u32(sK), sVu = smem_u32(sV), sPu = smem_u32(sP);

    // ---- S = Q K^T : each warp 16 rows x 256 cols ----
    float s[32][4];
    #pragma unroll
    for (int ni = 0; ni < 32; ni++)
        #pragma unroll
        for (int q = 0; q < 4; q++) s[ni][q] = 0.f;

    uint32_t a_row = (uint32_t)(wid*16 + (lane & 15)), a_koff = (uint32_t)(lane >> 4) * 8;
    uint32_t b_row = (uint32_t)(lane & 7), b_koff = (uint32_t)((lane >> 3) & 1) * 8;
    #pragma unroll
    for (int kk = 0; kk < 64; kk += 16) {
        uint32_t afr[4];
        ldm_x4(afr, sQu + (a_row*AT_QSTR + kk + a_koff)*2);
        #pragma unroll
        for (int ni = 0; ni < 32; ni++) {
            uint32_t bfr[2];
            ldm_x2(bfr, sKu + (((uint32_t)ni*8 + b_row)*AT_KSTR + kk + b_koff)*2);
            mma16816(s[ni], afr, bfr);
        }
    }

    // ---- bias + softmax (rows r0 = wid*16 + lane>>2 and r0+8) ----
    int rq = wid*16 + (lane >> 2);
    float tq0 = tv[q0 + rq];
    float tq1 = tv[q0 + rq + 8];
    float mx0 = -1e30f, mx1 = -1e30f;
    #pragma unroll
    for (int ni = 0; ni < 32; ni++) {
        #pragma unroll
        for (int c = 0; c < 2; c++) {
            float pos = ((float)(ni*8 + (lane & 3)*2 + c) + 0.5f) * (1.0f/256.0f);
            float d0 = tq0 - pos, d1 = tq1 - pos;
            s[ni][c]   = s[ni][c]*0.125f   - 10.0f*d0*d0;
            s[ni][c+2] = s[ni][c+2]*0.125f - 10.0f*d1*d1;
            mx0 = fmaxf(mx0, s[ni][c]);
            mx1 = fmaxf(mx1, s[ni][c+2]);
        }
    }
    #pragma unroll
    for (int o = 1; o < 4; o <<= 1) {
        mx0 = fmaxf(mx0, __shfl_xor_sync(0xffffffffu, mx0, o));
        mx1 = fmaxf(mx1, __shfl_xor_sync(0xffffffffu, mx1, o));
    }
    float den0 = 0.f, den1 = 0.f;
    #pragma unroll
    for (int ni = 0; ni < 32; ni++) {
        #pragma unroll
        for (int c = 0; c < 2; c++) {
            s[ni][c]   = __expf(s[ni][c]   - mx0);
            s[ni][c+2] = __expf(s[ni][c+2] - mx1);
            den0 += s[ni][c];
            den1 += s[ni][c+2];
        }
    }
    #pragma unroll
    for (int o = 1; o < 4; o <<= 1) {
        den0 += __shfl_xor_sync(0xffffffffu, den0, o);
        den1 += __shfl_xor_sync(0xffffffffu, den1, o);
    }
    float inv0 = 1.0f / den0, inv1 = 1.0f / den1;
    // store normalized P (fp16)
    int cbase = (lane & 3)*2;
    #pragma unroll
    for (int ni = 0; ni < 32; ni++) {
        *(__half2*)(sP + rq*AT_PSTR + ni*8 + cbase) =
            __floats2half2_rn(s[ni][0]*inv0, s[ni][1]*inv0);
        *(__half2*)(sP + (rq+8)*AT_PSTR + ni*8 + cbase) =
            __floats2half2_rn(s[ni][2]*inv1, s[ni][3]*inv1);
    }
    __syncthreads();

    // ---- O = P V : each warp 16 rows x 64 cols ----
    float o[8][4];
    #pragma unroll
    for (int nj = 0; nj < 8; nj++)
        #pragma unroll
        for (int q = 0; q < 4; q++) o[nj][q] = 0.f;

    #pragma unroll
    for (int kk = 0; kk < 256; kk += 16) {
        uint32_t afr[4];
        ldm_x4(afr, sPu + (a_row*AT_PSTR + kk + a_koff)*2);
        #pragma unroll
        for (int nj = 0; nj < 8; nj++) {
            uint32_t bfr[2];
            ldm_x2(bfr, sVu + (((uint32_t)nj*8 + b_row)*AT_VSTR + kk + b_koff)*2);
            mma16816(o[nj], afr, bfr);
        }
    }

    long long qi0 = q0 + rq;
    __half* op0 = out + ((size_t)b*HW + qi0)*FD + h*64;
    __half* op1 = op0 + (size_t)8*FD;
    #pragma unroll
    for (int nj = 0; nj < 8; nj++) {
        *(__half2*)(op0 + nj*8 + cbase) = __floats2half2_rn(o[nj][0], o[nj][1]);
        *(__half2*)(op1 + nj*8 + cbase) = __floats2half2_rn(o[nj][2], o[nj][3]);
    }
}

// ================= launch =================
#define TG_SMEM (4*STGH*2)   // 73728 bytes

extern "C" void kernel_launch(void* const* d_in, const int* in_sizes, int n_in,
                              void* d_out, int out_size)
{
    const float* x      = (const float*)d_in[0];
    const float* tokens = (const float*)d_in[1];
    const float* qW     = (const float*)d_in[2];
    const float* qb     = (const float*)d_in[3];
    const float* Wq     = (const float*)d_in[4];
    const float* Wkv    = (const float*)d_in[5];
    const float* Wo     = (const float*)d_in[6];
    const float* bo     = (const float*)d_in[7];
    const float* bwW    = (const float*)d_in[8];
    const float* bwb    = (const float*)d_in[9];
    const float* modW   = (const float*)d_in[10];
    const float* modb   = (const float*)d_in[11];
    const float* hvW    = (const float*)d_in[12];
    const float* hvb    = (const float*)d_in[13];
    const float* outW   = (const float*)d_in[14];
    const float* outb   = (const float*)d_in[15];
    float* total = (float*)d_out;

    __half *gqh, *glh, *xqh, *qh, *kvh, *attnh, *sh, *m0h, *hv1h, *tokh;
    __half *qWT, *WqT, *WkvT, *bwWT, *modWT, *hvWT, *WoA, *wfT;
    float *tv, *hl, *bfp;
    cudaGetSymbolAddress((void**)&gqh,   g_gq_h);
    cudaGetSymbolAddress((void**)&glh,   g_gl_h);
    cudaGetSymbolAddress((void**)&xqh,   g_xq_h);
    cudaGetSymbolAddress((void**)&qh,    g_q_h);
    cudaGetSymbolAddress((void**)&kvh,   g_kv_h);
    cudaGetSymbolAddress((void**)&attnh, g_attn_h);
    cudaGetSymbolAddress((void**)&sh,    g_s_h);
    cudaGetSymbolAddress((void**)&m0h,   g_m0_h);
    cudaGetSymbolAddress((void**)&hv1h,  g_hv1_h);
    cudaGetSymbolAddress((void**)&tokh,  g_tok_h);
    cudaGetSymbolAddress((void**)&qWT,   g_qWT);
    cudaGetSymbolAddress((void**)&WqT,   g_WqT);
    cudaGetSymbolAddress((void**)&WkvT,  g_WkvT);
    cudaGetSymbolAddress((void**)&bwWT,  g_bwWT);
    cudaGetSymbolAddress((void**)&modWT, g_modWT);
    cudaGetSymbolAddress((void**)&hvWT,  g_hvWT);
    cudaGetSymbolAddress((void**)&WoA,   g_WoA);
    cudaGetSymbolAddress((void**)&wfT,   g_wfT);
    cudaGetSymbolAddress((void**)&tv,    g_tv);
    cudaGetSymbolAddress((void**)&hl,    g_hl);
    cudaGetSymbolAddress((void**)&bfp,   g_bf);

    cudaFuncSetAttribute(tgemm<false,false,false,false>, cudaFuncAttributeMaxDynamicSharedMemorySize, TG_SMEM);
    cudaFuncSetAttribute(tgemm<true,false,false,false>,  cudaFuncAttributeMaxDynamicSharedMemorySize, TG_SMEM);
    cudaFuncSetAttribute(tgemm<true,true,false,true>,    cudaFuncAttributeMaxDynamicSharedMemorySize, TG_SMEM);
    cudaFuncSetAttribute(tgemm<true,true,true,false>,    cudaFuncAttributeMaxDynamicSharedMemorySize, TG_SMEM);
    cudaFuncSetAttribute(tgemm<true,false,false,true>,   cudaFuncAttributeMaxDynamicSharedMemorySize, TG_SMEM);
    cudaFuncSetAttribute(attn_mma_k, cudaFuncAttributeMaxDynamicSharedMemorySize, AT_SMEM);

    // 1) Fourier features + t values
    gamma_k<<<HW, 128>>>(x, gqh, glh, tv);

    // 2) weight prep
    transpose_h_k<<<(128*512+255)/256, 256>>>(qW, qWT, 128, 512);
    transpose_h_k<<<(512*128+255)/256, 256>>>(Wq, WqT, 512, 128);
    transpose_h_k<<<(512*256+255)/256, 256>>>(Wkv, WkvT, 512, 256);
    for (int i = 0; i < 3; i++)
        transpose_h_k<<<(128*512+255)/256, 256>>>(bwW + (size_t)i*128*512, bwWT + (size_t)i*512*128, 128, 512);
    for (int i = 0; i < 3; i++)
        transpose_h_k<<<(512*512+255)/256, 256>>>(modW + (size_t)i*512*512, modWT + (size_t)i*512*512, 512, 512);
    for (int i = 0; i < 2; i++)
        transpose_h_k<<<(512*512+255)/256, 256>>>(hvW + (size_t)i*512*512, hvWT + (size_t)i*512*512, 512, 512);
    convert_h_k<<<(128*512+255)/256, 256>>>(Wo, WoA, 128*512);
    convert_h_k<<<(NB*NTOK*HID+255)/256, 256>>>(tokens, tokh, NB*NTOK*HID);
    init_total_k<<<(MROWS*3+255)/256, 256>>>(outb, total);

    // 3) xq = relu(gq @ qW + qb) -> fp16
    tgemm<true,false,false,false><<<dim3(4,128), 256, TG_SMEM>>>(
        gqh, qWT, qb, nullptr, nullptr, nullptr, xqh, nullptr, nullptr, nullptr, HW, HID, FD);

    // 4) q = xq @ Wq -> fp16
    tgemm<false,false,false,false><<<dim3(1,128), 256, TG_SMEM>>>(
        xqh, WqT, nullptr, nullptr, nullptr, nullptr, qh, nullptr, nullptr, nullptr, HW, FD, HID);

    // 5) kv = tokens @ Wkv -> fp16
    tgemm<false,false,false,false><<<dim3(2,16), 256, TG_SMEM>>>(
        tokh, WkvT, nullptr, nullptr, nullptr, nullptr, kvh, nullptr, nullptr, nullptr, NB*NTOK, 256, HID);

    // 6) h_l[i] = relu(gl[i] @ bwW[i] + bwb[i]) -> fp32
    for (int i = 0; i < 3; i++)
        tgemm<true,false,false,false><<<dim3(4,128), 256, TG_SMEM>>>(
            glh + (size_t)i*HW*FD, bwWT + (size_t)i*HID*FD, bwb + i*HID,
            nullptr, nullptr, hl + (size_t)i*HW*HID, nullptr, nullptr, nullptr, nullptr, HW, HID, FD);

    // 7) wfT[i] = (Wo @ modW[i])^T -> fp16 [512][128]
    for (int i = 0; i < 3; i++)
        tgemm<false,false,false,false><<<dim3(4,1), 256, TG_SMEM>>>(
            WoA, modWT + (size_t)i*HID*HID, nullptr, nullptr, nullptr,
            nullptr, nullptr, wfT + (size_t)i*HID*FD, nullptr, nullptr, FD, HID, HID);
    bf_k<<<3, HID>>>(bo, modW, modb, bfp);

    // 8) attention (HMMA) -> fp16
    attn_mma_k<<<dim3(HW/128, 2, NB), 256, AT_SMEM>>>(qh, kvh, tv, attnh);

    // 9) M0 = relu(attn @ wf0 + bf0 + hl0) -> fp16 ; total += M0 @ outW0
    tgemm<true,true,false,true><<<dim3(4,1024), 256, TG_SMEM>>>(
        attnh, wfT, bfp, hl, nullptr, nullptr, m0h, nullptr, outW, total, MROWS, HID, FD);

    // 10) S1 = relu(attn @ wf1 + bf1 + hl1) + m0 -> fp16
    tgemm<true,true,true,false><<<dim3(4,1024), 256, TG_SMEM>>>(
        attnh, wfT + HID*FD, bfp + HID, hl + (size_t)HW*HID, m0h,
        nullptr, sh, nullptr, nullptr, nullptr, MROWS, HID, FD);

    // 11) HV1 = relu(S1 @ hvW0 + hvb0) -> fp16 ; total += HV1 @ outW1
    tgemm<true,false,false,true><<<dim3(4,1024), 256, TG_SMEM>>>(
        sh, hvWT, hvb, nullptr, nullptr, nullptr, hv1h, nullptr,
        outW + 512*3, total, MROWS, HID, HID);

    // 12) S2 = relu(attn @ wf2 + bf2 + hl2) + hv1 -> fp16
    tgemm<true,true,true,false><<<dim3(4,1024), 256, TG_SMEM>>>(
        attnh, wfT + 2*HID*FD, bfp + 2*HID, hl + 2ull*HW*HID, hv1h,
        nullptr, sh, nullptr, nullptr, nullptr, MROWS, HID, FD);

    // 13) HV2 = relu(S2 @ hvW1 + hvb1) ; total += HV2 @ outW2
    tgemm<true,false,false,true><<<dim3(4,1024), 256, TG_SMEM>>>(
        sh, hvWT + (size_t)HID*HID, hvb + HID, nullptr, nullptr, nullptr,
        nullptr, nullptr, outW + 2*512*3, total, MROWS, HID, HID);
}